// round 5
// baseline (speedup 1.0000x reference)
#include <cuda_runtime.h>
#include <cuda_fp16.h>
#include <cstdint>

#define IN_F  4096
#define OUT_F 4096
#define BATCH 4096

// ---------------- scratch (device globals: sanctioned no-alloc path) -------
__device__ __half g_wh[(size_t)OUT_F * IN_F];   // W as exact-int fp16
__device__ __half g_xh[(size_t)BATCH * IN_F];   // x as fp16
__device__ float  g_rowsum[BATCH];
__device__ float  g_biasf[OUT_F];
__device__ int    g_stats[2];      // wqmin, wqmax
__device__ int    g_tile_ctr;      // persistent-GEMM tile counter

// ---------------- helpers ---------------------------------------------------
__device__ __forceinline__ uint32_t smem_u32(const void* p) {
    uint32_t a;
    asm("{ .reg .u64 t; cvta.to.shared.u64 t, %1; cvt.u32.u64 %0, t; }"
        : "=r"(a) : "l"(p));
    return a;
}
__device__ __forceinline__ uint32_t sw128(uint32_t o) { return o ^ ((o >> 3) & 0x70); }

#define CP_ASYNC16(dst_u32, src_ptr) \
    asm volatile("cp.async.cg.shared.global [%0], [%1], 16;" \
                 :: "r"(dst_u32), "l"(src_ptr) : "memory")
#define CP_COMMIT()   asm volatile("cp.async.commit_group;" ::: "memory")
#define CP_WAIT2()    asm volatile("cp.async.wait_group 2;" ::: "memory")
#define CP_WAIT_ALL() asm volatile("cp.async.wait_group 0;" ::: "memory")

__device__ __forceinline__ void ldsm_x4(uint32_t& r0, uint32_t& r1,
                                        uint32_t& r2, uint32_t& r3,
                                        uint32_t addr) {
    asm volatile("ldmatrix.sync.aligned.m8n8.x4.shared.b16 {%0,%1,%2,%3}, [%4];"
                 : "=r"(r0), "=r"(r1), "=r"(r2), "=r"(r3) : "r"(addr));
}

__device__ __forceinline__ void mma_f16(float* c, const uint32_t* a,
                                        uint32_t b0, uint32_t b1) {
    asm volatile(
        "mma.sync.aligned.m16n8k16.row.col.f32.f16.f16.f32 "
        "{%0,%1,%2,%3}, {%4,%5,%6,%7}, {%8,%9}, {%0,%1,%2,%3};"
        : "+f"(c[0]), "+f"(c[1]), "+f"(c[2]), "+f"(c[3])
        : "r"(a[0]), "r"(a[1]), "r"(a[2]), "r"(a[3]), "r"(b0), "r"(b1));
}

// ---------------- preprocessing ---------------------------------------------
__global__ void k_init() {
    g_stats[0] = 0x7fffffff; g_stats[1] = (int)0x80000000;
    g_tile_ctr = 0;
}

// fused: W minmax + int32 -> exact fp16 conversion
__global__ void k_prepw(const int* __restrict__ wq) {
    size_t n4 = (size_t)OUT_F * IN_F / 4;
    int lmin = 0x7fffffff, lmax = (int)0x80000000;
    for (size_t idx = blockIdx.x * (size_t)blockDim.x + threadIdx.x; idx < n4;
         idx += (size_t)gridDim.x * blockDim.x) {
        int4 v = ((const int4*)wq)[idx];
        lmin = min(lmin, min(min(v.x, v.y), min(v.z, v.w)));
        lmax = max(lmax, max(max(v.x, v.y), max(v.z, v.w)));
        __half h[4];
        h[0] = __int2half_rn(v.x);
        h[1] = __int2half_rn(v.y);
        h[2] = __int2half_rn(v.z);
        h[3] = __int2half_rn(v.w);
        *((uint2*)&g_wh[idx * 4]) = *(uint2*)h;
    }
    for (int o = 16; o; o >>= 1) {
        lmin = min(lmin, __shfl_xor_sync(0xffffffffu, lmin, o));
        lmax = max(lmax, __shfl_xor_sync(0xffffffffu, lmax, o));
    }
    if ((threadIdx.x & 31) == 0) {
        atomicMin(&g_stats[0], lmin);
        atomicMax(&g_stats[1], lmax);
    }
}

// single-block fused bias minmax + dequant (self-contained)
__global__ void k_bias(const int* __restrict__ bq,
                       const float* __restrict__ pbmin,
                       const float* __restrict__ pbmax) {
    __shared__ int redmn[32], redmx[32];
    int tid = threadIdx.x;                     // 1024 threads
    int v[4];
    int lmin = 0x7fffffff, lmax = (int)0x80000000;
#pragma unroll
    for (int j = 0; j < 4; j++) {
        v[j] = bq[tid + j * 1024];
        lmin = min(lmin, v[j]); lmax = max(lmax, v[j]);
    }
    for (int o = 16; o; o >>= 1) {
        lmin = min(lmin, __shfl_xor_sync(0xffffffffu, lmin, o));
        lmax = max(lmax, __shfl_xor_sync(0xffffffffu, lmax, o));
    }
    if ((tid & 31) == 0) { redmn[tid >> 5] = lmin; redmx[tid >> 5] = lmax; }
    __syncthreads();
    if (tid < 32) {
        int a = redmn[tid], b = redmx[tid];
        for (int o = 16; o; o >>= 1) {
            a = min(a, __shfl_xor_sync(0xffffffffu, a, o));
            b = max(b, __shfl_xor_sync(0xffffffffu, b, o));
        }
        if (tid == 0) { redmn[0] = a; redmx[0] = b; }
    }
    __syncthreads();
    float bmn = *pbmin, bmx = *pbmax;
    float bsc = (bmx - bmn) / (float)(redmx[0] - redmn[0]);
    int qmn = redmn[0];
#pragma unroll
    for (int j = 0; j < 4; j++)
        g_biasf[tid + j * 1024] = (float)(v[j] - qmn) * bsc + bmn;
}

// x -> fp16 + fp32 row sum
__global__ void k_convx(const float* __restrict__ x) {
    int row = blockIdx.x;
    const float4* xr = (const float4*)(x + (size_t)row * IN_F);
    float s = 0.f;
    for (int i4 = threadIdx.x; i4 < IN_F / 4; i4 += blockDim.x) {
        float4 v = xr[i4];
        __half h[4];
        h[0] = __float2half_rn(v.x);
        h[1] = __float2half_rn(v.y);
        h[2] = __float2half_rn(v.z);
        h[3] = __float2half_rn(v.w);
        s += v.x + v.y + v.z + v.w;
        *((uint2*)&g_xh[(size_t)row * IN_F + i4 * 4]) = *(uint2*)h;
    }
    __shared__ float red[32];
    for (int o = 16; o; o >>= 1) s += __shfl_xor_sync(0xffffffffu, s, o);
    if ((threadIdx.x & 31) == 0) red[threadIdx.x >> 5] = s;
    __syncthreads();
    if (threadIdx.x < 32) {
        float t = (threadIdx.x < (blockDim.x >> 5)) ? red[threadIdx.x] : 0.f;
        for (int o = 16; o; o >>= 1) t += __shfl_xor_sync(0xffffffffu, t, o);
        if (threadIdx.x == 0) g_rowsum[row] = t;
    }
}

// ---------------- persistent GEMM (cp.async + ldmatrix + mma.sync) ----------
#define TM 128
#define TN 128
#define KC 64                        // fp16 K elems per chunk (128B rows)
#define NSTAGE 3
#define NK (IN_F / KC)               // 64 chunks
#define NTILES ((BATCH / TM) * (OUT_F / TN))   // 1024
#define NCTA 296                     // 148 SMs x 2 CTAs
#define A_BYTES (TM * 128)           // 16 KB
#define STAGE_BYTES (A_BYTES * 2)    // 32 KB
#define SMEM_TOTAL (NSTAGE * STAGE_BYTES)

__device__ __forceinline__ void load_chunk(int k, uint32_t sa, uint32_t sb,
                                           int m0, int n0, int tid) {
    int kk = k * KC;
#pragma unroll
    for (int j = 0; j < 4; j++) {          // A tile: 128 rows x 128B
        int u = tid + 256 * j;
        int row = u >> 3, seg = u & 7;
        const void* src = g_xh + (size_t)(m0 + row) * IN_F + kk + seg * 8;
        CP_ASYNC16(sa + sw128((uint32_t)(row * 128 + seg * 16)), src);
    }
#pragma unroll
    for (int j = 0; j < 4; j++) {          // B tile: 128 rows x 128B
        int u = tid + 256 * j;
        int row = u >> 3, seg = u & 7;
        const void* src = g_wh + (size_t)(n0 + row) * IN_F + kk + seg * 8;
        CP_ASYNC16(sb + sw128((uint32_t)(row * 128 + seg * 16)), src);
    }
}

__global__ void __launch_bounds__(256, 2) k_gemm(
    float* __restrict__ out,
    const float* __restrict__ p_wmin, const float* __restrict__ p_wmax) {
    extern __shared__ __align__(1024) char smem[];
    __shared__ int s_tile;
    uint32_t sbase = smem_u32(smem);
    const int tid = threadIdx.x;
    const int wid = tid >> 5;
    const int lid = tid & 31;
    const int wm = wid & 3;          // 4 warps along M  -> 32-row warp tile
    const int wn = wid >> 2;         // 2 warps along N  -> 64-col warp tile

    const float wmn = *p_wmin, wmx = *p_wmax;
    const float ws = (wmx - wmn) / (float)(g_stats[1] - g_stats[0]);
    const float alpha0 = wmn - ws * (float)g_stats[0];

    const int rlane = lid & 15;
    const int chalf = (lid >> 4) << 4;

    for (;;) {
        if (tid == 0) s_tile = atomicAdd(&g_tile_ctr, 1);
        __syncthreads();
        int tile = s_tile;
        if (tile >= NTILES) { CP_WAIT_ALL(); break; }
        const int m0 = (tile & 31) * TM;        // consecutive tiles share n0
        const int n0 = (tile >> 5) * TN;

        float acc[2][8][4];
#pragma unroll
        for (int i = 0; i < 2; i++)
#pragma unroll
            for (int j = 0; j < 8; j++)
#pragma unroll
                for (int e = 0; e < 4; e++) acc[i][j][e] = 0.f;

        // prologue: fill all 3 stages
#pragma unroll
        for (int s = 0; s < NSTAGE; s++) {
            uint32_t sa = sbase + s * STAGE_BYTES;
            load_chunk(s, sa, sa + A_BYTES, m0, n0, tid);
            CP_COMMIT();
        }

        for (int k = 0; k < NK; k++) {
            CP_WAIT2();
            __syncthreads();
            uint32_t sa = sbase + (k % NSTAGE) * STAGE_BYTES;
            uint32_t sb = sa + A_BYTES;

#pragma unroll
            for (int ks = 0; ks < 4; ks++) {
                uint32_t a[2][4], b[4][4];
#pragma unroll
                for (int mi = 0; mi < 2; mi++) {
                    int row = wm * 32 + mi * 16 + rlane;
                    ldsm_x4(a[mi][0], a[mi][1], a[mi][2], a[mi][3],
                            sa + sw128((uint32_t)(row * 128 + ks * 32 + chalf)));
                }
#pragma unroll
                for (int ng = 0; ng < 4; ng++) {
                    int row = wn * 64 + ng * 16 + rlane;
                    ldsm_x4(b[ng][0], b[ng][1], b[ng][2], b[ng][3],
                            sb + sw128((uint32_t)(row * 128 + ks * 32 + chalf)));
                }
#pragma unroll
                for (int mi = 0; mi < 2; mi++)
#pragma unroll
                    for (int ng = 0; ng < 4; ng++) {
                        mma_f16(acc[mi][ng * 2 + 0], a[mi], b[ng][0], b[ng][2]);
                        mma_f16(acc[mi][ng * 2 + 1], a[mi], b[ng][1], b[ng][3]);
                    }
            }
            __syncthreads();
            if (k + NSTAGE < NK) {
                load_chunk(k + NSTAGE, sa, sb, m0, n0, tid);
            }
            CP_COMMIT();   // keep pending-group count fixed
        }

        // ---- epilogue: fold scales, rowsum correction, bias ---------------
        const int rm = m0 + wm * 32;
        const int cn = n0 + wn * 64;
        float fb[16];
#pragma unroll
        for (int jn = 0; jn < 8; jn++) {
            int col = cn + jn * 8 + (lid & 3) * 2;
            float2 b2 = *(const float2*)&g_biasf[col];
            fb[jn * 2] = b2.x; fb[jn * 2 + 1] = b2.y;
        }
#pragma unroll
        for (int mi = 0; mi < 2; mi++) {
            int r0 = rm + mi * 16 + (lid >> 2);
            float radd0 = alpha0 * g_rowsum[r0];
            float radd1 = alpha0 * g_rowsum[r0 + 8];
#pragma unroll
            for (int jn = 0; jn < 8; jn++) {
                int col = cn + jn * 8 + (lid & 3) * 2;
                const float* c = acc[mi][jn];
                float2 o0, o1;
                o0.x = ws * c[0] + radd0 + fb[jn * 2];
                o0.y = ws * c[1] + radd0 + fb[jn * 2 + 1];
                o1.x = ws * c[2] + radd1 + fb[jn * 2];
                o1.y = ws * c[3] + radd1 + fb[jn * 2 + 1];
                *(float2*)&out[(size_t)r0 * OUT_F + col] = o0;
                *(float2*)&out[(size_t)(r0 + 8) * OUT_F + col] = o1;
            }
        }
        __syncthreads();   // all warps done with smem + s_tile before next tile
    }
}

// ---------------- launch ----------------------------------------------------
extern "C" void kernel_launch(void* const* d_in, const int* in_sizes, int n_in,
                              void* d_out, int out_size) {
    const float* x    = (const float*)d_in[0];
    const int*   wq   = (const int*)d_in[1];
    const int*   bq   = (const int*)d_in[2];
    const float* wmin = (const float*)d_in[3];
    const float* wmax = (const float*)d_in[4];
    const float* bmin = (const float*)d_in[5];
    const float* bmax = (const float*)d_in[6];
    float* out = (float*)d_out;

    cudaFuncSetAttribute(k_gemm, cudaFuncAttributeMaxDynamicSharedMemorySize,
                         SMEM_TOTAL);

    k_init<<<1, 1>>>();
    k_prepw<<<2048, 256>>>(wq);
    k_bias<<<1, 1024>>>(bq, bmin, bmax);
    k_convx<<<BATCH, 256>>>(x);

    k_gemm<<<NCTA, 256, SMEM_TOTAL>>>(out, wmin, wmax);
}

// round 7
// speedup vs baseline: 1.0479x; 1.0479x over previous
#include <cuda_runtime.h>
#include <cuda_fp16.h>
#include <cstdint>

#define IN_F  4096
#define OUT_F 4096
#define BATCH 4096

// ---------------- scratch (device globals: sanctioned no-alloc path) -------
__device__ __half g_wh[(size_t)OUT_F * IN_F];   // W as exact-int fp16
__device__ __half g_xh[(size_t)BATCH * IN_F];   // x as fp16
__device__ float  g_rowsum[BATCH];
__device__ float  g_biasf[OUT_F];
__device__ int    g_stats[2];          // wqmin, wqmax (final)
__device__ int    g_wpart[2048 * 2];   // per-block W min/max partials

// ---------------- helpers ---------------------------------------------------
__device__ __forceinline__ uint32_t smem_u32(const void* p) {
    uint32_t a;
    asm("{ .reg .u64 t; cvta.to.shared.u64 t, %1; cvt.u32.u64 %0, t; }"
        : "=r"(a) : "l"(p));
    return a;
}
__device__ __forceinline__ uint32_t sw128(uint32_t o) { return o ^ ((o >> 3) & 0x70); }

#define CP_ASYNC16(dst_u32, src_ptr) \
    asm volatile("cp.async.cg.shared.global [%0], [%1], 16;" \
                 :: "r"(dst_u32), "l"(src_ptr) : "memory")
#define CP_COMMIT()   asm volatile("cp.async.commit_group;" ::: "memory")
#define CP_WAIT2()    asm volatile("cp.async.wait_group 2;" ::: "memory")

__device__ __forceinline__ void ldsm_x4(uint32_t& r0, uint32_t& r1,
                                        uint32_t& r2, uint32_t& r3,
                                        uint32_t addr) {
    asm volatile("ldmatrix.sync.aligned.m8n8.x4.shared.b16 {%0,%1,%2,%3}, [%4];"
                 : "=r"(r0), "=r"(r1), "=r"(r2), "=r"(r3) : "r"(addr));
}

__device__ __forceinline__ void mma_f16(float* c, const uint32_t* a,
                                        uint32_t b0, uint32_t b1) {
    asm volatile(
        "mma.sync.aligned.m16n8k16.row.col.f32.f16.f16.f32 "
        "{%0,%1,%2,%3}, {%4,%5,%6,%7}, {%8,%9}, {%0,%1,%2,%3};"
        : "+f"(c[0]), "+f"(c[1]), "+f"(c[2]), "+f"(c[3])
        : "r"(a[0]), "r"(a[1]), "r"(a[2]), "r"(a[3]), "r"(b0), "r"(b1));
}

// ---------------- preprocessing ---------------------------------------------
// W minmax (atomics-free per-block partials) + int32 -> exact fp16 conversion
__global__ void k_prepw(const int* __restrict__ wq) {
    size_t n4 = (size_t)OUT_F * IN_F / 4;
    int lmin = 0x7fffffff, lmax = (int)0x80000000;
    for (size_t idx = blockIdx.x * (size_t)blockDim.x + threadIdx.x; idx < n4;
         idx += (size_t)gridDim.x * blockDim.x) {
        int4 v = ((const int4*)wq)[idx];
        lmin = min(lmin, min(min(v.x, v.y), min(v.z, v.w)));
        lmax = max(lmax, max(max(v.x, v.y), max(v.z, v.w)));
        __half h[4];
        h[0] = __int2half_rn(v.x);
        h[1] = __int2half_rn(v.y);
        h[2] = __int2half_rn(v.z);
        h[3] = __int2half_rn(v.w);
        *((uint2*)&g_wh[idx * 4]) = *(uint2*)h;
    }
    __shared__ int smn[32], smx[32];
    for (int o = 16; o; o >>= 1) {
        lmin = min(lmin, __shfl_xor_sync(0xffffffffu, lmin, o));
        lmax = max(lmax, __shfl_xor_sync(0xffffffffu, lmax, o));
    }
    if ((threadIdx.x & 31) == 0) { smn[threadIdx.x >> 5] = lmin; smx[threadIdx.x >> 5] = lmax; }
    __syncthreads();
    if (threadIdx.x < 32) {
        int a = (threadIdx.x < 8) ? smn[threadIdx.x] : 0x7fffffff;
        int b = (threadIdx.x < 8) ? smx[threadIdx.x] : (int)0x80000000;
        for (int o = 4; o; o >>= 1) {
            a = min(a, __shfl_xor_sync(0xffffffffu, a, o));
            b = max(b, __shfl_xor_sync(0xffffffffu, b, o));
        }
        if (threadIdx.x == 0) {
            g_wpart[blockIdx.x * 2]     = a;
            g_wpart[blockIdx.x * 2 + 1] = b;
        }
    }
}

// fused: x->fp16 + rowsum (blocks 0..4095), bias dequant (block 4096),
// W-stats partial reduction (block 4097)
__global__ void k_convx(const float* __restrict__ x,
                        const int* __restrict__ bq,
                        const float* __restrict__ pbmin,
                        const float* __restrict__ pbmax) {
    int bid = blockIdx.x;
    if (bid < BATCH) {
        int row = bid;
        const float4* xr = (const float4*)(x + (size_t)row * IN_F);
        float s = 0.f;
        for (int i4 = threadIdx.x; i4 < IN_F / 4; i4 += blockDim.x) {
            float4 v = xr[i4];
            __half h[4];
            h[0] = __float2half_rn(v.x);
            h[1] = __float2half_rn(v.y);
            h[2] = __float2half_rn(v.z);
            h[3] = __float2half_rn(v.w);
            s += v.x + v.y + v.z + v.w;
            *((uint2*)&g_xh[(size_t)row * IN_F + i4 * 4]) = *(uint2*)h;
        }
        __shared__ float red[32];
        for (int o = 16; o; o >>= 1) s += __shfl_xor_sync(0xffffffffu, s, o);
        if ((threadIdx.x & 31) == 0) red[threadIdx.x >> 5] = s;
        __syncthreads();
        if (threadIdx.x < 32) {
            float t = (threadIdx.x < (blockDim.x >> 5)) ? red[threadIdx.x] : 0.f;
            for (int o = 16; o; o >>= 1) t += __shfl_xor_sync(0xffffffffu, t, o);
            if (threadIdx.x == 0) g_rowsum[row] = t;
        }
    } else if (bid == BATCH) {
        // bias: minmax + dequant, 256 threads x 16 elems
        __shared__ int redmn[32], redmx[32];
        int tid = threadIdx.x;
        int v[16];
        int lmin = 0x7fffffff, lmax = (int)0x80000000;
#pragma unroll
        for (int j = 0; j < 16; j++) {
            v[j] = bq[tid + j * 256];
            lmin = min(lmin, v[j]); lmax = max(lmax, v[j]);
        }
        for (int o = 16; o; o >>= 1) {
            lmin = min(lmin, __shfl_xor_sync(0xffffffffu, lmin, o));
            lmax = max(lmax, __shfl_xor_sync(0xffffffffu, lmax, o));
        }
        if ((tid & 31) == 0) { redmn[tid >> 5] = lmin; redmx[tid >> 5] = lmax; }
        __syncthreads();
        if (tid < 32) {
            int a = (tid < 8) ? redmn[tid] : 0x7fffffff;
            int b = (tid < 8) ? redmx[tid] : (int)0x80000000;
            for (int o = 4; o; o >>= 1) {
                a = min(a, __shfl_xor_sync(0xffffffffu, a, o));
                b = max(b, __shfl_xor_sync(0xffffffffu, b, o));
            }
            if (tid == 0) { redmn[0] = a; redmx[0] = b; }
        }
        __syncthreads();
        float bmn = *pbmin, bmx = *pbmax;
        float bsc = (bmx - bmn) / (float)(redmx[0] - redmn[0]);
        int qmn = redmn[0];
#pragma unroll
        for (int j = 0; j < 16; j++)
            g_biasf[tid + j * 256] = (float)(v[j] - qmn) * bsc + bmn;
    } else {
        // reduce W partials (2048 blocks) -> g_stats
        int tid = threadIdx.x;   // 256 threads x 8 partials
        int lmin = 0x7fffffff, lmax = (int)0x80000000;
#pragma unroll
        for (int j = 0; j < 8; j++) {
            int p = tid + j * 256;
            lmin = min(lmin, g_wpart[p * 2]);
            lmax = max(lmax, g_wpart[p * 2 + 1]);
        }
        __shared__ int redmn[32], redmx[32];
        for (int o = 16; o; o >>= 1) {
            lmin = min(lmin, __shfl_xor_sync(0xffffffffu, lmin, o));
            lmax = max(lmax, __shfl_xor_sync(0xffffffffu, lmax, o));
        }
        if ((tid & 31) == 0) { redmn[tid >> 5] = lmin; redmx[tid >> 5] = lmax; }
        __syncthreads();
        if (tid < 32) {
            int a = (tid < 8) ? redmn[tid] : 0x7fffffff;
            int b = (tid < 8) ? redmx[tid] : (int)0x80000000;
            for (int o = 4; o; o >>= 1) {
                a = min(a, __shfl_xor_sync(0xffffffffu, a, o));
                b = max(b, __shfl_xor_sync(0xffffffffu, b, o));
            }
            if (tid == 0) { g_stats[0] = a; g_stats[1] = b; }
        }
    }
}

// ---------------- GEMM: 128 thr/CTA, 2x2 warps, 64x64 warp tile -------------
#define TM 128
#define TN 128
#define KC 64                        // fp16 K elems per chunk (128B rows)
#define NSTAGE 3
#define NK (IN_F / KC)               // 64 chunks
#define A_BYTES (TM * 128)           // 16 KB
#define STAGE_BYTES (A_BYTES * 2)    // 32 KB
#define SMEM_TOTAL (NSTAGE * STAGE_BYTES)

__device__ __forceinline__ void load_chunk(int k, uint32_t sa, uint32_t sb,
                                           int m0, int n0, int tid) {
    int kk = k * KC;
#pragma unroll
    for (int j = 0; j < 8; j++) {          // A tile: 128 rows x 128B
        int u = tid + 128 * j;
        int row = u >> 3, seg = u & 7;
        const void* src = g_xh + (size_t)(m0 + row) * IN_F + kk + seg * 8;
        CP_ASYNC16(sa + sw128((uint32_t)(row * 128 + seg * 16)), src);
    }
#pragma unroll
    for (int j = 0; j < 8; j++) {          // B tile: 128 rows x 128B
        int u = tid + 128 * j;
        int row = u >> 3, seg = u & 7;
        const void* src = g_wh + (size_t)(n0 + row) * IN_F + kk + seg * 8;
        CP_ASYNC16(sb + sw128((uint32_t)(row * 128 + seg * 16)), src);
    }
}

__global__ void __launch_bounds__(128, 2) k_gemm(
    float* __restrict__ out,
    const float* __restrict__ p_wmin, const float* __restrict__ p_wmax) {
    extern __shared__ __align__(1024) char smem[];
    uint32_t sbase = smem_u32(smem);
    const int tid = threadIdx.x;
    const int wid = tid >> 5;
    const int lid = tid & 31;
    const int wm = wid >> 1;         // 2 warps along M -> 64-row warp tile
    const int wn = wid & 1;          // 2 warps along N -> 64-col warp tile
    const int m0 = blockIdx.y * TM;
    const int n0 = blockIdx.x * TN;

    float acc[4][8][4];
#pragma unroll
    for (int i = 0; i < 4; i++)
#pragma unroll
        for (int j = 0; j < 8; j++)
#pragma unroll
            for (int e = 0; e < 4; e++) acc[i][j][e] = 0.f;

    // prologue: fill all 3 stages
#pragma unroll
    for (int s = 0; s < NSTAGE; s++) {
        uint32_t sa = sbase + s * STAGE_BYTES;
        load_chunk(s, sa, sa + A_BYTES, m0, n0, tid);
        CP_COMMIT();
    }

    const int rlane = lid & 15;
    const int chalf = (lid >> 4) << 4;

    for (int k = 0; k < NK; k++) {
        CP_WAIT2();
        __syncthreads();
        uint32_t sa = sbase + (k % NSTAGE) * STAGE_BYTES;
        uint32_t sb = sa + A_BYTES;

#pragma unroll
        for (int ks = 0; ks < 4; ks++) {
            uint32_t a[4][4], b[4][4];
#pragma unroll
            for (int mi = 0; mi < 4; mi++) {
                int row = wm * 64 + mi * 16 + rlane;
                ldsm_x4(a[mi][0], a[mi][1], a[mi][2], a[mi][3],
                        sa + sw128((uint32_t)(row * 128 + ks * 32 + chalf)));
            }
#pragma unroll
            for (int ng = 0; ng < 4; ng++) {
                int row = wn * 64 + ng * 16 + rlane;
                ldsm_x4(b[ng][0], b[ng][1], b[ng][2], b[ng][3],
                        sb + sw128((uint32_t)(row * 128 + ks * 32 + chalf)));
            }
#pragma unroll
            for (int mi = 0; mi < 4; mi++)
#pragma unroll
                for (int ng = 0; ng < 4; ng++) {
                    mma_f16(acc[mi][ng * 2 + 0], a[mi], b[ng][0], b[ng][2]);
                    mma_f16(acc[mi][ng * 2 + 1], a[mi], b[ng][1], b[ng][3]);
                }
        }
        __syncthreads();
        if (k + NSTAGE < NK) {
            load_chunk(k + NSTAGE, sa, sb, m0, n0, tid);
        }
        CP_COMMIT();   // keep pending-group count fixed
    }

    // ---- epilogue: fold scales, rowsum correction, bias -------------------
    const float wmn = *p_wmin, wmx = *p_wmax;
    const float ws = (wmx - wmn) / (float)(g_stats[1] - g_stats[0]);
    const float alpha0 = wmn - ws * (float)g_stats[0];

    const int rm = m0 + wm * 64;
    const int cn = n0 + wn * 64;
    float fb[16];
#pragma unroll
    for (int jn = 0; jn < 8; jn++) {
        int col = cn + jn * 8 + (lid & 3) * 2;
        float2 b2 = *(const float2*)&g_biasf[col];
        fb[jn * 2] = b2.x; fb[jn * 2 + 1] = b2.y;
    }
#pragma unroll
    for (int mi = 0; mi < 4; mi++) {
        int r0 = rm + mi * 16 + (lid >> 2);
        float radd0 = alpha0 * g_rowsum[r0];
        float radd1 = alpha0 * g_rowsum[r0 + 8];
#pragma unroll
        for (int jn = 0; jn < 8; jn++) {
            int col = cn + jn * 8 + (lid & 3) * 2;
            const float* c = acc[mi][jn];
            float2 o0, o1;
            o0.x = ws * c[0] + radd0 + fb[jn * 2];
            o0.y = ws * c[1] + radd0 + fb[jn * 2 + 1];
            o1.x = ws * c[2] + radd1 + fb[jn * 2];
            o1.y = ws * c[3] + radd1 + fb[jn * 2 + 1];
            *(float2*)&out[(size_t)r0 * OUT_F + col] = o0;
            *(float2*)&out[(size_t)(r0 + 8) * OUT_F + col] = o1;
        }
    }
}

// ---------------- launch ----------------------------------------------------
extern "C" void kernel_launch(void* const* d_in, const int* in_sizes, int n_in,
                              void* d_out, int out_size) {
    const float* x    = (const float*)d_in[0];
    const int*   wq   = (const int*)d_in[1];
    const int*   bq   = (const int*)d_in[2];
    const float* wmin = (const float*)d_in[3];
    const float* wmax = (const float*)d_in[4];
    const float* bmin = (const float*)d_in[5];
    const float* bmax = (const float*)d_in[6];
    float* out = (float*)d_out;

    cudaFuncSetAttribute(k_gemm, cudaFuncAttributeMaxDynamicSharedMemorySize,
                         SMEM_TOTAL);

    k_prepw<<<2048, 256>>>(wq);                       // launch 1
    k_convx<<<BATCH + 2, 256>>>(x, bq, bmin, bmax);   // launch 2
    dim3 grid(OUT_F / TN, BATCH / TM);
    k_gemm<<<grid, 128, SMEM_TOTAL>>>(out, wmin, wmax);  // launch 3
}